// round 3
// baseline (speedup 1.0000x reference)
#include <cuda_runtime.h>
#include <math.h>

#define NN    576
#define MR    144
#define RD    15
#define EDGES (MR * RD)         // 2160
#define BATCH 256
#define ITERS 3
#define SUBS  2                 // batch elements per decode block
#define TPB   (MR * SUBS)       // 288 threads
#define CPT   (NN / MR)         // 4 columns owned per thread

// Row-major edge structure
__device__ int g_cols[EDGES];   // column index of edge (row, j)
__device__ int g_dst[EDGES];    // slot of edge in column-major edge array
// Column CSR
__device__ int g_colptr[NN];
__device__ int g_deg[NN];

// P1: warp-per-row ballot compaction of H rows -> g_cols (ascending order).
__global__ void ldpc_prep_rows(const float* __restrict__ H) {
    const int m    = blockIdx.x;
    const int lane = threadIdx.x;
    const float* row = H + m * NN;
    int cnt = 0;
    #pragma unroll
    for (int base = 0; base < NN; base += 32) {
        float v = row[base + lane];
        unsigned mask = __ballot_sync(0xFFFFFFFFu, v == 1.0f);
        if (v == 1.0f) {
            int pos = cnt + __popc(mask & ((1u << lane) - 1u));
            g_cols[m * RD + pos] = base + lane;
        }
        cnt += __popc(mask);
    }
}

// P2: one block of NN threads. Histogram g_cols -> degrees, exclusive scan ->
// colptr, then assign each edge its column-major slot.
__global__ void ldpc_prep_cols() {
    __shared__ int hist[NN];
    __shared__ int scn[NN];
    const int t = threadIdx.x;

    hist[t] = 0;
    __syncthreads();
    for (int e = t; e < EDGES; e += NN) atomicAdd(&hist[g_cols[e]], 1);
    __syncthreads();

    // Hillis-Steele inclusive scan over NN
    int v = hist[t];
    scn[t] = v;
    __syncthreads();
    for (int off = 1; off < NN; off <<= 1) {
        int add = (t >= off) ? scn[t - off] : 0;
        __syncthreads();
        scn[t] += add;
        __syncthreads();
    }
    int excl = scn[t] - v;
    g_colptr[t] = excl;
    g_deg[t]    = v;

    hist[t] = excl;   // running fill pointer
    __syncthreads();
    for (int e = t; e < EDGES; e += NN) {
        int n = g_cols[e];
        g_dst[e] = atomicAdd(&hist[n], 1);
    }
}

// Decode: one block = SUBS batch elements; thread = one check row AND owner of
// CPT consecutive columns. No shared atomics: rows scatter E into a
// column-major edge array via precomputed slots; columns gather+sum.
__global__ __launch_bounds__(TPB, 1)
void ldpc_decode_kernel(const float* __restrict__ r,
                        const float* __restrict__ alpha,
                        const float* __restrict__ beta,
                        float* __restrict__ out) {
    __shared__ float V[SUBS][NN];       // posterior r + colsum(E)
    __shared__ float E_sh[SUBS][EDGES]; // column-major edge messages

    const int t   = threadIdx.x;
    const int sub = t / MR;
    const int row = t - sub * MR;       // check row, also column-group owner
    const int b   = blockIdx.x * SUBS + sub;
    const int c0  = row * CPT;          // first owned column

    float a_[ITERS], bt_[ITERS];
    #pragma unroll
    for (int it = 0; it < ITERS; it++) { a_[it] = alpha[it]; bt_[it] = beta[it]; }

    // Owned-column channel values (float4, coalesced) + CSR ranges.
    const float4 rv = *reinterpret_cast<const float4*>(r + b * NN + c0);
    float rc[CPT] = {rv.x, rv.y, rv.z, rv.w};
    int cp[CPT], cd[CPT];
    #pragma unroll
    for (int k = 0; k < CPT; k++) { cp[k] = g_colptr[c0 + k]; cd[k] = g_deg[c0 + k]; }

    // Init V = r.
    reinterpret_cast<float4*>(&V[sub][0])[row] = rv;

    // Row-side edge data.
    int   cols[RD], dst[RD];
    float Eprev[RD];
    #pragma unroll
    for (int j = 0; j < RD; j++) {
        cols[j]  = g_cols[row * RD + j];
        dst[j]   = g_dst[row * RD + j];
        Eprev[j] = 0.0f;
    }
    __syncthreads();

    #pragma unroll
    for (int it = 0; it < ITERS; it++) {
        const float a  = a_[it];
        const float bt = bt_[it];

        // ---- row phase: extrinsic messages, min1/min2/argmin, sign product ----
        float am[RD];
        unsigned sb[RD];
        unsigned sgn = 0u;
        #pragma unroll
        for (int j = 0; j < RD; j++) {
            float m = V[sub][cols[j]] - Eprev[j];
            unsigned mu = __float_as_uint(m);
            sb[j] = mu & 0x80000000u;
            sgn  ^= sb[j];
            am[j] = fabsf(m);
        }
        // two-chain min reduction + merge (halved dependency depth)
        float a1 = INFINITY, a2 = INFINITY; int ja = 0;
        #pragma unroll
        for (int j = 0; j < 8; j++) {
            if (am[j] < a1) { a2 = a1; a1 = am[j]; ja = j; }
            else if (am[j] < a2) { a2 = am[j]; }
        }
        float b1 = INFINITY, b2 = INFINITY; int jb = 8;
        #pragma unroll
        for (int j = 8; j < RD; j++) {
            if (am[j] < b1) { b2 = b1; b1 = am[j]; jb = j; }
            else if (am[j] < b2) { b2 = am[j]; }
        }
        int   jmin = (a1 <= b1) ? ja : jb;
        float min1 = fminf(a1, b1);
        float min2 = (a1 <= b1) ? fminf(a2, b1) : fminf(b2, a1);

        const float mag1 = a * fmaxf(0.0f, min1 - bt);
        const float mag2 = a * fmaxf(0.0f, min2 - bt);

        #pragma unroll
        for (int j = 0; j < RD; j++) {
            float mag = (j == jmin) ? mag2 : mag1;
            float e = __uint_as_float(__float_as_uint(mag) ^ (sgn ^ sb[j]));
            Eprev[j] = e;
            E_sh[sub][dst[j]] = e;
        }
        __syncthreads();   // edges ready; V reads complete

        // ---- column phase: gather-sum owned columns ----
        if (it < ITERS - 1) {
            float4 vn;
            float* vp = &vn.x;
            #pragma unroll
            for (int k = 0; k < CPT; k++) {
                float s = rc[k];
                int p = cp[k], e = cd[k];
                for (int q = 0; q < e; q++) s += E_sh[sub][p + q];
                vp[k] = s;
            }
            reinterpret_cast<float4*>(&V[sub][0])[row] = vn;
            __syncthreads();   // V ready for next row phase
        } else {
            // final posterior -> straight to global (coalesced float4)
            float4 vn;
            float* vp = &vn.x;
            #pragma unroll
            for (int k = 0; k < CPT; k++) {
                float s = rc[k];
                int p = cp[k], e = cd[k];
                for (int q = 0; q < e; q++) s += E_sh[sub][p + q];
                vp[k] = s;
            }
            *reinterpret_cast<float4*>(out + b * NN + c0) = vn;
        }
    }
}

extern "C" void kernel_launch(void* const* d_in, const int* in_sizes, int n_in,
                              void* d_out, int out_size) {
    const float* r     = (const float*)d_in[0];   // (256, 576)
    const float* H     = (const float*)d_in[1];   // (144, 576)
    const float* alpha = (const float*)d_in[2];   // (3,)
    const float* beta  = (const float*)d_in[3];   // (3,)
    float* out = (float*)d_out;                   // (256, 576)

    ldpc_prep_rows<<<MR, 32>>>(H);
    ldpc_prep_cols<<<1, NN>>>();
    ldpc_decode_kernel<<<BATCH / SUBS, TPB>>>(r, alpha, beta, out);
}

// round 4
// speedup vs baseline: 1.3375x; 1.3375x over previous
#include <cuda_runtime.h>
#include <math.h>

#define NN     576
#define MR     144
#define RD     15
#define EDGES  (MR * RD)        // 2160
#define BATCH  256
#define ITERS  3
#define CPT    (NN / MR)        // 4 columns owned per thread
#define MAXDEG 18               // column-degree bound (binomial mean 3.75; P(>18) ~ 0)

// Column indices of the 15 ones in each of the 144 rows of H.
__device__ int g_cols[EDGES];

// Prep: one block per row, 576 threads, one coalesced load each.
// Ballot per warp + single-warp scan of the 18 warp counts -> ordered compaction.
__global__ void ldpc_prep(const float* __restrict__ H) {
    __shared__ int woff[18];
    const int m = blockIdx.x;
    const int t = threadIdx.x;
    const int w = t >> 5, l = t & 31;

    const float v = H[m * NN + t];
    const unsigned mask = __ballot_sync(0xFFFFFFFFu, v == 1.0f);
    if (l == 0) woff[w] = __popc(mask);
    __syncthreads();
    if (w == 0) {
        int orig = (l < 18) ? woff[l] : 0;
        int c = orig;
        #pragma unroll
        for (int off = 1; off < 32; off <<= 1) {
            int x = __shfl_up_sync(0xFFFFFFFFu, c, off);
            if (l >= off) c += x;
        }
        if (l < 18) woff[l] = c - orig;   // exclusive prefix
    }
    __syncthreads();
    if (v == 1.0f) {
        int pos = woff[w] + __popc(mask & ((1u << l) - 1u));
        g_cols[m * RD + pos] = t;
    }
}

// Decode: one block per batch element; thread = one check row AND owner of the
// 4 columns {row + k*144}. Rows scatter extrinsic messages into a transposed
// column-slot array (slot = q*NN + col, q assigned once via shared atomics);
// columns gather+sum conflict-free. No atomics in the iteration loop.
__global__ __launch_bounds__(MR, 4)
void ldpc_decode_kernel(const float* __restrict__ r,
                        const float* __restrict__ alpha,
                        const float* __restrict__ beta,
                        float* __restrict__ out) {
    __shared__ float V[NN];             // posterior r + colsum(E)
    __shared__ float E_sh[MAXDEG * NN]; // transposed column-major edge messages
    __shared__ int   fill[NN];          // per-column fill counters -> degrees

    const int row = threadIdx.x;        // 0..143
    const int b   = blockIdx.x;

    float a_[ITERS], bt_[ITERS];
    #pragma unroll
    for (int it = 0; it < ITERS; it++) { a_[it] = alpha[it]; bt_[it] = beta[it]; }

    // Owned-column channel values (coalesced per k); init V and fill.
    float rc[CPT];
    #pragma unroll
    for (int k = 0; k < CPT; k++) {
        int n = row + k * MR;
        float v = r[b * NN + n];
        rc[k]   = v;
        V[n]    = v;
        fill[n] = 0;
    }

    int cols[RD];
    float Eprev[RD];
    #pragma unroll
    for (int j = 0; j < RD; j++) {
        cols[j]  = g_cols[row * RD + j];
        Eprev[j] = 0.0f;
    }
    __syncthreads();

    // One-time slot assignment: unique slot per edge within its column.
    int slot[RD];
    #pragma unroll
    for (int j = 0; j < RD; j++) {
        int q = atomicAdd(&fill[cols[j]], 1);
        slot[j] = q * NN + cols[j];
    }
    __syncthreads();

    int cd[CPT];
    #pragma unroll
    for (int k = 0; k < CPT; k++) cd[k] = fill[row + k * MR];

    #pragma unroll
    for (int it = 0; it < ITERS; it++) {
        const float a  = a_[it];
        const float bt = bt_[it];

        // ---- row phase: extrinsic msgs, min1/min2/argmin, sign (XOR of sign bits) ----
        float am[RD];
        unsigned sb[RD];
        unsigned sgn = 0u;
        #pragma unroll
        for (int j = 0; j < RD; j++) {
            float m = V[cols[j]] - Eprev[j];
            unsigned mu = __float_as_uint(m);
            sb[j] = mu & 0x80000000u;
            sgn  ^= sb[j];
            am[j] = fabsf(m);
        }
        // two-chain min1/min2 reduction + merge
        float a1 = INFINITY, a2 = INFINITY; int ja = 0;
        #pragma unroll
        for (int j = 0; j < 8; j++) {
            if (am[j] < a1) { a2 = a1; a1 = am[j]; ja = j; }
            else if (am[j] < a2) { a2 = am[j]; }
        }
        float b1 = INFINITY, b2 = INFINITY; int jb = 8;
        #pragma unroll
        for (int j = 8; j < RD; j++) {
            if (am[j] < b1) { b2 = b1; b1 = am[j]; jb = j; }
            else if (am[j] < b2) { b2 = am[j]; }
        }
        const int   jmin = (a1 <= b1) ? ja : jb;
        const float min1 = fminf(a1, b1);
        const float min2 = (a1 <= b1) ? fminf(a2, b1) : fminf(b2, a1);

        const float mag1 = a * fmaxf(0.0f, min1 - bt);
        const float mag2 = a * fmaxf(0.0f, min2 - bt);

        #pragma unroll
        for (int j = 0; j < RD; j++) {
            float mag = (j == jmin) ? mag2 : mag1;
            float e = __uint_as_float(__float_as_uint(mag) ^ (sgn ^ sb[j]));
            Eprev[j] = e;
            E_sh[slot[j]] = e;
        }
        __syncthreads();   // edges published; all V reads done

        // ---- column phase: conflict-free gather-sum of owned columns ----
        if (it < ITERS - 1) {
            #pragma unroll
            for (int k = 0; k < CPT; k++) {
                int n = row + k * MR;
                float s = rc[k];
                for (int q = 0; q < cd[k]; q++) s += E_sh[q * NN + n];
                V[n] = s;
            }
            __syncthreads();   // V ready for next row phase
        } else {
            #pragma unroll
            for (int k = 0; k < CPT; k++) {
                int n = row + k * MR;
                float s = rc[k];
                for (int q = 0; q < cd[k]; q++) s += E_sh[q * NN + n];
                out[b * NN + n] = s;   // coalesced final store
            }
        }
    }
}

extern "C" void kernel_launch(void* const* d_in, const int* in_sizes, int n_in,
                              void* d_out, int out_size) {
    const float* r     = (const float*)d_in[0];   // (256, 576)
    const float* H     = (const float*)d_in[1];   // (144, 576)
    const float* alpha = (const float*)d_in[2];   // (3,)
    const float* beta  = (const float*)d_in[3];   // (3,)
    float* out = (float*)d_out;                   // (256, 576)

    ldpc_prep<<<MR, NN>>>(H);
    ldpc_decode_kernel<<<BATCH, MR>>>(r, alpha, beta, out);
}